// round 10
// baseline (speedup 1.0000x reference)
#include <cuda_runtime.h>
#include <cuda_fp16.h>

#define NPIX 16384   // 128*128 ROI pixels
#define NS   64      // sensors
#define NT   2030    // time samples
#define NB   64      // batch
#define SNT  (NS*NT) // 129920

// Transposed fp16 sinogram: [s][t][b]  (16.6 MB -> L2-resident)
__device__ __half g_t16[NS * NT * NB];
__device__ float  g_bmax[NB];

// Transpose+quantize: sino [b][s*t] fp32 -> g_t16 [s*t][b] fp16.
__global__ __launch_bounds__(512) void transpose_kernel(
    const float* __restrict__ sino)
{
    __shared__ float tile[64][65];
    const int st0 = blockIdx.x * 64;
    const int tid = threadIdx.x;
    const int l   = tid & 31;
    const int w   = tid >> 5;

    if (blockIdx.x == 0 && tid < NB) g_bmax[tid] = 0.0f;

    #pragma unroll
    for (int k = 0; k < 4; ++k) {
        const int r = w * 4 + k;
        float2 v = *reinterpret_cast<const float2*>(
            sino + (size_t)r * SNT + st0 + 2 * l);
        tile[r][2 * l]     = v.x;
        tile[r][2 * l + 1] = v.y;
    }
    __syncthreads();

    unsigned int* __restrict__ dst = reinterpret_cast<unsigned int*>(g_t16);
    #pragma unroll
    for (int k = 0; k < 4; ++k) {
        const int st = w * 4 + k;
        __half2 h = __floats2half2_rn(tile[2 * l][st], tile[2 * l + 1][st]);
        dst[(size_t)(st0 + st) * 32 + l] = *reinterpret_cast<unsigned int*>(&h);
    }
}

// Block = 512 thr = 16 pixel-warps. Gather: warp = pixel, lane = batch-pair
// (one dense 128B line per (pix,s)). Store (after conflict-free exchange):
// thread = (batch, pixel); 2 batches per thread via h-loop.
__global__ __launch_bounds__(512) void das_kernel(
    const float* __restrict__ wts,    // [NPIX][NS]
    const int*   __restrict__ tidx,   // [NPIX][NS]
    float*       __restrict__ out)    // [NB*NPIX das | NB*NS*NPIX pixel_interp]
{
    __shared__ int   sm_off[16][64];      // (s*NT+t)*32 half2-row offsets
    __shared__ float sm_w  [16][64];
    __shared__ float ex[2][2][16][33];    // [buf][plane][pix][bpair]

    const int tid = threadIdx.x;
    const int l   = tid & 31;
    const int w   = tid >> 5;             // 0..15: gather pixel
    const int px0 = blockIdx.x * 16;

    // store-role coordinates
    const int sb  = tid >> 4;             // 0..31: batch (plus 32*h)
    const int sp  = tid & 15;             // pixel within tile

    // ---- preload geometry: 16 pixels x 64 sensors (coalesced) ----
    #pragma unroll
    for (int h = 0; h < 2; ++h) {
        const int e  = tid + h * 512;
        const int pp = e >> 6;
        const int s  = e & 63;
        int   t = tidx[(px0 + pp) * NS + s];
        float v = wts [(px0 + pp) * NS + s];
        v = (t >= 0 && t < NT) ? v : 0.0f;
        t = min(max(t, 0), NT - 1);
        sm_off[pp][s] = (s * NT + t) * 32;
        sm_w  [pp][s] = v;
    }
    __syncthreads();

    const unsigned int* __restrict__ g2 =
        reinterpret_cast<const unsigned int*>(g_t16);
    float* __restrict__ pi = out + NB * NPIX;
    float2 acc = make_float2(0.0f, 0.0f);

    // prologue: gather s=0
    unsigned int hraw = __ldg(g2 + sm_off[w][0] + l);
    float        wt   = sm_w[w][0];

    for (int s = 0; s < NS; ++s) {
        // prefetch next sensor's gather (overlaps exchange+stores)
        unsigned int hn = 0; float wn = 0.0f;
        if (s + 1 < NS) {
            hn = __ldg(g2 + sm_off[w][s + 1] + l);
            wn = sm_w[w][s + 1];
        }

        __half2 hh = *reinterpret_cast<__half2*>(&hraw);
        float2  v  = __half22float2(hh);
        v.x *= wt; v.y *= wt;
        acc.x += v.x; acc.y += v.y;

        const int p = s & 1;
        ex[p][0][w][l] = v.x;             // batch 2l
        ex[p][1][w][l] = v.y;             // batch 2l+1
        __syncthreads();                  // single barrier (double-buffered)

        // store role: batches sb, sb+32 at pixel px0+sp (64B segments)
        #pragma unroll
        for (int h = 0; h < 2; ++h) {
            const int bb = sb + 32 * h;
            const float u = ex[p][bb & 1][sp][bb >> 1];
            __stcs(pi + ((size_t)bb * NS + s) * NPIX + px0 + sp, u);
        }
        hraw = hn; wt = wn;
    }

    // ---- das epilogue: exchange acc, relu, store, per-batch max ----
    __syncthreads();
    ex[0][0][w][l] = acc.x;
    ex[0][1][w][l] = acc.y;
    __syncthreads();
    #pragma unroll
    for (int h = 0; h < 2; ++h) {
        const int bb = sb + 32 * h;
        float d = fmaxf(ex[0][bb & 1][sp][bb >> 1], 0.0f);
        __stcs(out + (size_t)bb * NPIX + px0 + sp, d);
        // reduce over the 16 pixels held by this half-warp
        #pragma unroll
        for (int off = 8; off > 0; off >>= 1)
            d = fmaxf(d, __shfl_xor_sync(0xffffffffu, d, off));
        if (sp == 0)
            atomicMax(reinterpret_cast<int*>(&g_bmax[bb]), __float_as_int(d));
    }
}

__global__ __launch_bounds__(256) void norm_kernel(float* __restrict__ out)
{
    int i = blockIdx.x * blockDim.x + threadIdx.x;
    float4* p = reinterpret_cast<float4*>(out);
    float4 v = p[i];
    int b = (i * 4) >> 14;
    float m = g_bmax[b];
    float r = (m > 1e-8f) ? (1.0f / m) : 1.0f;
    v.x *= r; v.y *= r; v.z *= r; v.w *= r;
    p[i] = v;
}

extern "C" void kernel_launch(void* const* d_in, const int* in_sizes, int n_in,
                              void* d_out, int out_size)
{
    const float* sino = (const float*)d_in[0];   // [64,1,64,2030]
    const float* wts  = (const float*)d_in[1];   // [128,128,64]
    const int*   tidx = (const int*)d_in[2];     // [128,128,64]
    float* out = (float*)d_out;

    transpose_kernel<<<SNT / 64, 512>>>(sino);          // 2030 blocks

    das_kernel<<<NPIX / 16, 512>>>(wts, tidx, out);     // 1024 blocks

    norm_kernel<<<(NB * NPIX / 4) / 256, 256>>>(out);
}

// round 11
// speedup vs baseline: 1.0786x; 1.0786x over previous
#include <cuda_runtime.h>
#include <cuda_fp16.h>

#define NPIX 16384   // 128*128 ROI pixels
#define NS   64      // sensors
#define NT   2030    // time samples
#define NB   64      // batch
#define SNT  (NS*NT) // 129920

// Transposed fp16 sinogram: [s][t][b]  (16.6 MB -> L2-resident)
__device__ __half g_t16[NS * NT * NB];
__device__ float  g_bmax[NB];

// Transpose+quantize: sino [b][s*t] fp32 -> g_t16 [s*t][b] fp16.
__global__ __launch_bounds__(512) void transpose_kernel(
    const float* __restrict__ sino)
{
    __shared__ float tile[64][65];
    const int st0 = blockIdx.x * 64;
    const int tid = threadIdx.x;
    const int l   = tid & 31;
    const int w   = tid >> 5;

    if (blockIdx.x == 0 && tid < NB) g_bmax[tid] = 0.0f;

    #pragma unroll
    for (int k = 0; k < 4; ++k) {
        const int r = w * 4 + k;
        float2 v = *reinterpret_cast<const float2*>(
            sino + (size_t)r * SNT + st0 + 2 * l);
        tile[r][2 * l]     = v.x;
        tile[r][2 * l + 1] = v.y;
    }
    __syncthreads();

    unsigned int* __restrict__ dst = reinterpret_cast<unsigned int*>(g_t16);
    #pragma unroll
    for (int k = 0; k < 4; ++k) {
        const int st = w * 4 + k;
        __half2 h = __floats2half2_rn(tile[2 * l][st], tile[2 * l + 1][st]);
        dst[(size_t)(st0 + st) * 32 + l] = *reinterpret_cast<unsigned int*>(&h);
    }
}

// Block = 1024 thr = 32 warps, 64-pixel tile (two 32-px groups).
// Gather: warp = pixel pair {w, w+32}, lane = batch-pair (dense 128B lines).
// Store: warp = batches {2w, 2w+1}, 256B contiguous per (b,s) per block.
__global__ __launch_bounds__(1024) void das_kernel(
    const float* __restrict__ wts,    // [NPIX][NS]
    const int*   __restrict__ tidx,   // [NPIX][NS]
    float*       __restrict__ out)    // [NB*NPIX das | NB*NS*NPIX pixel_interp]
{
    __shared__ int   sm_off[64][64];          // (s*NT+t)*32 half2-row offsets
    __shared__ float sm_w  [64][64];
    __shared__ float ex[2][2][2][32][33];     // [buf][group][plane][w][l]

    const int tid = threadIdx.x;
    const int l   = tid & 31;
    const int w   = tid >> 5;
    const int px0 = blockIdx.x * 64;

    // ---- preload geometry: 64 pixels x 64 sensors (coalesced) ----
    #pragma unroll
    for (int k = 0; k < 4; ++k) {
        const int e  = tid + k * 1024;
        const int pp = e >> 6;
        const int s  = e & 63;
        int   t = tidx[(px0 + pp) * NS + s];
        float v = wts [(px0 + pp) * NS + s];
        v = (t >= 0 && t < NT) ? v : 0.0f;
        t = min(max(t, 0), NT - 1);
        sm_off[pp][s] = (s * NT + t) * 32;
        sm_w  [pp][s] = v;
    }
    __syncthreads();

    const unsigned int* __restrict__ g2 =
        reinterpret_cast<const unsigned int*>(g_t16);
    float* __restrict__ pi = out + NB * NPIX;
    float2 acc0 = make_float2(0.0f, 0.0f);   // pixel w
    float2 acc1 = make_float2(0.0f, 0.0f);   // pixel w+32

    // prologue: gather s=0 for both pixel groups
    unsigned int h0 = __ldg(g2 + sm_off[w][0]      + l);
    unsigned int h1 = __ldg(g2 + sm_off[w + 32][0] + l);
    float        w0 = sm_w[w][0];
    float        w1 = sm_w[w + 32][0];

    for (int s = 0; s < NS; ++s) {
        // prefetch next sensor (overlaps exchange+stores)
        unsigned int h0n = 0, h1n = 0; float w0n = 0.0f, w1n = 0.0f;
        if (s + 1 < NS) {
            h0n = __ldg(g2 + sm_off[w][s + 1]      + l);
            h1n = __ldg(g2 + sm_off[w + 32][s + 1] + l);
            w0n = sm_w[w][s + 1];
            w1n = sm_w[w + 32][s + 1];
        }

        float2 v0 = __half22float2(*reinterpret_cast<__half2*>(&h0));
        float2 v1 = __half22float2(*reinterpret_cast<__half2*>(&h1));
        v0.x *= w0; v0.y *= w0;  acc0.x += v0.x; acc0.y += v0.y;
        v1.x *= w1; v1.y *= w1;  acc1.x += v1.x; acc1.y += v1.y;

        const int p = s & 1;
        ex[p][0][0][w][l] = v0.x;     // group0, batch 2l
        ex[p][0][1][w][l] = v0.y;     // group0, batch 2l+1
        ex[p][1][0][w][l] = v1.x;     // group1, batch 2l
        ex[p][1][1][w][l] = v1.y;     // group1, batch 2l+1
        __syncthreads();              // single barrier (double-buffered)

        // store role: batches 2w, 2w+1; 256B contiguous span per (b,s)
        #pragma unroll
        for (int hb = 0; hb < 2; ++hb) {
            const int bb = 2 * w + hb;
            const size_t o = ((size_t)bb * NS + s) * NPIX + px0 + l;
            __stcs(pi + o,      ex[p][0][hb][l][w]);
            __stcs(pi + o + 32, ex[p][1][hb][l][w]);
        }
        h0 = h0n; h1 = h1n; w0 = w0n; w1 = w1n;
    }

    // ---- das epilogue: exchange acc, relu, store, per-batch max ----
    __syncthreads();
    ex[0][0][0][w][l] = acc0.x;
    ex[0][0][1][w][l] = acc0.y;
    ex[0][1][0][w][l] = acc1.x;
    ex[0][1][1][w][l] = acc1.y;
    __syncthreads();
    #pragma unroll
    for (int hb = 0; hb < 2; ++hb) {
        const int bb = 2 * w + hb;
        float d0 = fmaxf(ex[0][0][hb][l][w], 0.0f);
        float d1 = fmaxf(ex[0][1][hb][l][w], 0.0f);
        __stcs(out + (size_t)bb * NPIX + px0 + l,      d0);
        __stcs(out + (size_t)bb * NPIX + px0 + 32 + l, d1);
        float m = fmaxf(d0, d1);
        #pragma unroll
        for (int off = 16; off > 0; off >>= 1)
            m = fmaxf(m, __shfl_xor_sync(0xffffffffu, m, off));
        if (l == 0)
            atomicMax(reinterpret_cast<int*>(&g_bmax[bb]), __float_as_int(m));
    }
}

__global__ __launch_bounds__(256) void norm_kernel(float* __restrict__ out)
{
    int i = blockIdx.x * blockDim.x + threadIdx.x;
    float4* p = reinterpret_cast<float4*>(out);
    float4 v = p[i];
    int b = (i * 4) >> 14;
    float m = g_bmax[b];
    float r = (m > 1e-8f) ? (1.0f / m) : 1.0f;
    v.x *= r; v.y *= r; v.z *= r; v.w *= r;
    p[i] = v;
}

extern "C" void kernel_launch(void* const* d_in, const int* in_sizes, int n_in,
                              void* d_out, int out_size)
{
    const float* sino = (const float*)d_in[0];   // [64,1,64,2030]
    const float* wts  = (const float*)d_in[1];   // [128,128,64]
    const int*   tidx = (const int*)d_in[2];     // [128,128,64]
    float* out = (float*)d_out;

    transpose_kernel<<<SNT / 64, 512>>>(sino);          // 2030 blocks

    das_kernel<<<NPIX / 64, 1024>>>(wts, tidx, out);    // 256 blocks

    norm_kernel<<<(NB * NPIX / 4) / 256, 256>>>(out);
}

// round 12
// speedup vs baseline: 1.0882x; 1.0089x over previous
#include <cuda_runtime.h>
#include <cuda_fp16.h>

#define NPIX 16384   // 128*128 ROI pixels
#define NS   64      // sensors
#define NT   2030    // time samples
#define NB   64      // batch
#define SNT  (NS*NT) // 129920

// Transposed fp16 sinogram: [s][t][b]  (16.6 MB -> L2-resident)
__device__ __half g_t16[NS * NT * NB];
__device__ float  g_bmax[NB];

// Transpose+quantize: sino [b][s*t] fp32 -> g_t16 [s*t][b] fp16.
// XOR-swizzled tile: elem (r=batch, c=st) at r*64 + (c ^ ((r>>1)&31)).
// STS banks: (c ^ const) bijective in lane. LDS banks: (st ^ l) bijective.
__global__ __launch_bounds__(512) void transpose_kernel(
    const float* __restrict__ sino)
{
    __shared__ float tile[64 * 64];
    const int st0 = blockIdx.x * 64;
    const int tid = threadIdx.x;
    const int l   = tid & 31;
    const int w   = tid >> 5;

    if (blockIdx.x == 0 && tid < NB) g_bmax[tid] = 0.0f;

    #pragma unroll
    for (int k = 0; k < 4; ++k) {
        const int r = w * 4 + k;                 // batch row
        const int sw = (r >> 1) & 31;
        float2 v = *reinterpret_cast<const float2*>(
            sino + (size_t)r * SNT + st0 + 2 * l);
        tile[r * 64 + ((2 * l)     ^ sw)] = v.x;
        tile[r * 64 + ((2 * l + 1) ^ sw)] = v.y;
    }
    __syncthreads();

    unsigned int* __restrict__ dst = reinterpret_cast<unsigned int*>(g_t16);
    #pragma unroll
    for (int k = 0; k < 4; ++k) {
        const int st = w * 4 + k;
        const int cs = st ^ (l & 31);
        __half2 h = __floats2half2_rn(tile[(2 * l) * 64 + cs],
                                      tile[(2 * l + 1) * 64 + cs]);
        dst[(size_t)(st0 + st) * 32 + l] = *reinterpret_cast<unsigned int*>(&h);
    }
}

// Block = 1024 thr = 32 warps, 64-pixel tile (two 32-px groups).
// Gather: warp = pixel pair {w, w+32}, lane = batch-pair (dense 128B lines).
// Store: warp = batches {2w, 2w+1}, 256B contiguous per (b,s) per block.
__global__ __launch_bounds__(1024) void das_kernel(
    const float* __restrict__ wts,    // [NPIX][NS]
    const int*   __restrict__ tidx,   // [NPIX][NS]
    float*       __restrict__ out)    // [NB*NPIX das | NB*NS*NPIX pixel_interp]
{
    __shared__ int   sm_off[64][64];          // (s*NT+t)*32 half2-row offsets
    __shared__ float sm_w  [64][64];
    __shared__ float ex[2][2][2][32][33];     // [buf][group][plane][w][l]

    const int tid = threadIdx.x;
    const int l   = tid & 31;
    const int w   = tid >> 5;
    const int px0 = blockIdx.x * 64;

    // ---- preload geometry: 64 pixels x 64 sensors (coalesced) ----
    #pragma unroll
    for (int k = 0; k < 4; ++k) {
        const int e  = tid + k * 1024;
        const int pp = e >> 6;
        const int s  = e & 63;
        int   t = tidx[(px0 + pp) * NS + s];
        float v = wts [(px0 + pp) * NS + s];
        v = (t >= 0 && t < NT) ? v : 0.0f;
        t = min(max(t, 0), NT - 1);
        sm_off[pp][s] = (s * NT + t) * 32;
        sm_w  [pp][s] = v;
    }
    __syncthreads();

    const unsigned int* __restrict__ g2 =
        reinterpret_cast<const unsigned int*>(g_t16);
    float* __restrict__ pi = out + NB * NPIX;
    float2 acc0 = make_float2(0.0f, 0.0f);   // pixel w
    float2 acc1 = make_float2(0.0f, 0.0f);   // pixel w+32

    // prologue: gather s=0 for both pixel groups
    unsigned int h0 = __ldg(g2 + sm_off[w][0]      + l);
    unsigned int h1 = __ldg(g2 + sm_off[w + 32][0] + l);
    float        w0 = sm_w[w][0];
    float        w1 = sm_w[w + 32][0];

    for (int s = 0; s < NS; ++s) {
        // prefetch next sensor (overlaps exchange+stores)
        unsigned int h0n = 0, h1n = 0; float w0n = 0.0f, w1n = 0.0f;
        if (s + 1 < NS) {
            h0n = __ldg(g2 + sm_off[w][s + 1]      + l);
            h1n = __ldg(g2 + sm_off[w + 32][s + 1] + l);
            w0n = sm_w[w][s + 1];
            w1n = sm_w[w + 32][s + 1];
        }

        float2 v0 = __half22float2(*reinterpret_cast<__half2*>(&h0));
        float2 v1 = __half22float2(*reinterpret_cast<__half2*>(&h1));
        v0.x *= w0; v0.y *= w0;  acc0.x += v0.x; acc0.y += v0.y;
        v1.x *= w1; v1.y *= w1;  acc1.x += v1.x; acc1.y += v1.y;

        const int p = s & 1;
        ex[p][0][0][w][l] = v0.x;     // group0, batch 2l
        ex[p][0][1][w][l] = v0.y;     // group0, batch 2l+1
        ex[p][1][0][w][l] = v1.x;     // group1, batch 2l
        ex[p][1][1][w][l] = v1.y;     // group1, batch 2l+1
        __syncthreads();              // single barrier (double-buffered)

        // store role: batches 2w, 2w+1; 256B contiguous span per (b,s)
        #pragma unroll
        for (int hb = 0; hb < 2; ++hb) {
            const int bb = 2 * w + hb;
            const size_t o = ((size_t)bb * NS + s) * NPIX + px0 + l;
            __stcs(pi + o,      ex[p][0][hb][l][w]);
            __stcs(pi + o + 32, ex[p][1][hb][l][w]);
        }
        h0 = h0n; h1 = h1n; w0 = w0n; w1 = w1n;
    }

    // ---- das epilogue: exchange acc, relu, store (write-back: stays in L2
    //      for norm_kernel), per-batch max ----
    __syncthreads();
    ex[0][0][0][w][l] = acc0.x;
    ex[0][0][1][w][l] = acc0.y;
    ex[0][1][0][w][l] = acc1.x;
    ex[0][1][1][w][l] = acc1.y;
    __syncthreads();
    #pragma unroll
    for (int hb = 0; hb < 2; ++hb) {
        const int bb = 2 * w + hb;
        float d0 = fmaxf(ex[0][0][hb][l][w], 0.0f);
        float d1 = fmaxf(ex[0][1][hb][l][w], 0.0f);
        out[(size_t)bb * NPIX + px0 + l]      = d0;
        out[(size_t)bb * NPIX + px0 + 32 + l] = d1;
        float m = fmaxf(d0, d1);
        #pragma unroll
        for (int off = 16; off > 0; off >>= 1)
            m = fmaxf(m, __shfl_xor_sync(0xffffffffu, m, off));
        if (l == 0)
            atomicMax(reinterpret_cast<int*>(&g_bmax[bb]), __float_as_int(m));
    }
}

__global__ __launch_bounds__(256) void norm_kernel(float* __restrict__ out)
{
    int i = blockIdx.x * blockDim.x + threadIdx.x;
    float4* p = reinterpret_cast<float4*>(out);
    float4 v = p[i];
    int b = (i * 4) >> 14;
    float m = g_bmax[b];
    float r = (m > 1e-8f) ? (1.0f / m) : 1.0f;
    v.x *= r; v.y *= r; v.z *= r; v.w *= r;
    p[i] = v;
}

extern "C" void kernel_launch(void* const* d_in, const int* in_sizes, int n_in,
                              void* d_out, int out_size)
{
    const float* sino = (const float*)d_in[0];   // [64,1,64,2030]
    const float* wts  = (const float*)d_in[1];   // [128,128,64]
    const int*   tidx = (const int*)d_in[2];     // [128,128,64]
    float* out = (float*)d_out;

    transpose_kernel<<<SNT / 64, 512>>>(sino);          // 2030 blocks

    das_kernel<<<NPIX / 64, 1024>>>(wts, tidx, out);    // 256 blocks

    norm_kernel<<<(NB * NPIX / 4) / 256, 256>>>(out);
}